// round 14
// baseline (speedup 1.0000x reference)
#include <cuda_runtime.h>
#include <math.h>
#include <stdint.h>

// Problem constants
#define BB 64
#define TT 512
#define DD 512
#define UU 1024
#define G4 4096          // 4*UU
#define LN_EPS 1e-3f

// ---------------------------------------------------------------------------
// Scratch (device globals — no allocation allowed)
// ---------------------------------------------------------------------------
__device__ float g_zx[(size_t)BB * TT * G4];     // 512 MiB, reused by both layers
__device__ float g_hseq[(size_t)BB * TT * UU];   // 128 MiB
// packed R^T as A-frags: [block 128][kt 128][mt 2][lane 32][4]  (tf32-hi)
__device__ float g_rp2[(size_t)128 * 128 * 2 * 32 * 4];   // 16 MiB
// packed h^T as B-frags: [kt 128][nt 8][lane 32][2 slots], ping/pong
__device__ float g_hp_hi[2][128 * 8 * 32 * 2];   // 256KB each
__device__ float g_hlast[BB * UU];
// two-level barrier: 8 group counters on separate 128B lines + root + epoch
__device__ __align__(128) unsigned g_cnt[8][32];
__device__ __align__(128) unsigned g_root[32];
__device__ __align__(128) unsigned g_epoch[32];

// ---------------------------------------------------------------------------
// Helpers
// ---------------------------------------------------------------------------
__device__ __forceinline__ float cvt_tf32(float a) {
    float r;
    asm("cvt.rna.tf32.f32 %0, %1;" : "=f"(r) : "f"(a));
    return r;
}

__device__ __forceinline__ void cp16(void* s, const void* g) {
    uint32_t sa = (uint32_t)__cvta_generic_to_shared(s);
    asm volatile("cp.async.cg.shared.global [%0], [%1], 16;" :: "r"(sa), "l"(g));
}
#define CP_COMMIT()  asm volatile("cp.async.commit_group;" ::: "memory")
#define CP_WAIT(n)   asm volatile("cp.async.wait_group %0;" :: "n"(n) : "memory")

#define MMA_TF32(d, a, b0v, b1v) \
    asm volatile("mma.sync.aligned.m16n8k8.row.col.f32.tf32.tf32.f32 " \
        "{%0,%1,%2,%3}, {%4,%5,%6,%7}, {%8,%9}, {%0,%1,%2,%3};" \
        : "+f"((d)[0]), "+f"((d)[1]), "+f"((d)[2]), "+f"((d)[3]) \
        : "r"((a)[0]), "r"((a)[1]), "r"((a)[2]), "r"((a)[3]), \
          "r"(b0v), "r"(b1v))

// ===========================================================================
// Pack R^T (tf32-hi) into per-block A-frag layout (unchanged).
// ===========================================================================
__global__ __launch_bounds__(256)
void pack_r3_kernel(const float* __restrict__ R, float* __restrict__ Rp)
{
    int i = blockIdx.x * blockDim.x + threadIdx.x;   // float4 index (2^20 total)
    int lane = i & 31;
    int mt   = (i >> 5) & 1;
    int kt   = (i >> 6) & 127;
    int b    = i >> 13;
    int g  = lane >> 2, ii = lane & 3;
    int m0 = mt * 16 + g, m1 = m0 + 8;
    int col0 = (m0 >> 3) * UU + b * 8 + (m0 & 7);
    int col1 = (m1 >> 3) * UU + b * 8 + (m1 & 7);
    int r0 = kt * 8 + ii;
    float4 o;
    o.x = cvt_tf32(__ldg(&R[(size_t)r0 * G4 + col0]));
    o.y = cvt_tf32(__ldg(&R[(size_t)r0 * G4 + col1]));
    o.z = cvt_tf32(__ldg(&R[(size_t)(r0 + 4) * G4 + col0]));
    o.w = cvt_tf32(__ldg(&R[(size_t)(r0 + 4) * G4 + col1]));
    *(float4*)&Rp[(size_t)i * 4] = o;
}

// ===========================================================================
// 2xTF32 GEMM (Ah*Bh + Ah*Bl), cp.async double-buffered (unchanged)
// ===========================================================================
#define GBK   32
#define A_LD  36
#define B_LD  136
#define ASZ   (128 * A_LD)
#define BSZ   (GBK * B_LD)
#define GEMM_SMEM_BYTES (2 * (ASZ + BSZ) * 4)   // 71680 B

__global__ __launch_bounds__(256, 2)
void gemm_tf32_kernel(const float* __restrict__ A, const float* __restrict__ W,
                      const float* __restrict__ bias, float* __restrict__ C,
                      int M, int N, int K)
{
    extern __shared__ float sm[];
    float* Asm[2] = { sm, sm + ASZ };
    float* Bsm[2] = { sm + 2 * ASZ, sm + 2 * ASZ + BSZ };

    const int tid  = threadIdx.x;
    const int m0   = blockIdx.y * 128;
    const int n0   = blockIdx.x * 128;
    const int lane = tid & 31, wid = tid >> 5;
    const int wm   = (wid & 3) * 32;
    const int wn   = (wid >> 2) * 64;
    const int g    = lane >> 2, ii = lane & 3;

    const int a_r = tid >> 3, a_c = (tid & 7) * 4;
    const int b_r = tid >> 5, b_c = (tid & 31) * 4;

    float acc[2][8][4];
    #pragma unroll
    for (int mi = 0; mi < 2; mi++)
        #pragma unroll
        for (int ni = 0; ni < 8; ni++)
            #pragma unroll
            for (int q = 0; q < 4; q++) acc[mi][ni][q] = 0.f;

    const int nk = K >> 5;

    {
        #pragma unroll
        for (int p = 0; p < 4; p++)
            cp16(&Asm[0][(a_r + p * 32) * A_LD + a_c],
                 &A[(size_t)(m0 + a_r + p * 32) * K + a_c]);
        #pragma unroll
        for (int p = 0; p < 4; p++)
            cp16(&Bsm[0][(b_r + p * 8) * B_LD + b_c],
                 &W[(size_t)(b_r + p * 8) * N + n0 + b_c]);
        CP_COMMIT();
    }

    for (int ch = 0; ch < nk; ch++) {
        const int buf = ch & 1;
        if (ch + 1 < nk) {
            const int k0 = (ch + 1) << 5;
            #pragma unroll
            for (int p = 0; p < 4; p++)
                cp16(&Asm[buf ^ 1][(a_r + p * 32) * A_LD + a_c],
                     &A[(size_t)(m0 + a_r + p * 32) * K + k0 + a_c]);
            #pragma unroll
            for (int p = 0; p < 4; p++)
                cp16(&Bsm[buf ^ 1][(b_r + p * 8) * B_LD + b_c],
                     &W[(size_t)(k0 + b_r + p * 8) * N + n0 + b_c]);
            CP_COMMIT();
            CP_WAIT(1);
        } else {
            CP_WAIT(0);
        }
        __syncthreads();

        const float* Ab = Asm[buf];
        const float* Bb = Bsm[buf];
        #pragma unroll
        for (int ks = 0; ks < 4; ks++) {
            const int kb = ks * 8;
            uint32_t ah[2][4];
            #pragma unroll
            for (int mi = 0; mi < 2; mi++) {
                int r0 = (wm + mi * 16 + g) * A_LD + kb + ii;
                int r8 = r0 + 8 * A_LD;
                ah[mi][0] = __float_as_uint(cvt_tf32(Ab[r0]));
                ah[mi][1] = __float_as_uint(cvt_tf32(Ab[r8]));
                ah[mi][2] = __float_as_uint(cvt_tf32(Ab[r0 + 4]));
                ah[mi][3] = __float_as_uint(cvt_tf32(Ab[r8 + 4]));
            }
            #pragma unroll
            for (int ni = 0; ni < 8; ni++) {
                int nb = wn + ni * 8 + g;
                float w0 = Bb[(kb + ii) * B_LD + nb];
                float w1 = Bb[(kb + ii + 4) * B_LD + nb];
                float bh0f = cvt_tf32(w0), bh1f = cvt_tf32(w1);
                uint32_t bh0 = __float_as_uint(bh0f);
                uint32_t bh1 = __float_as_uint(bh1f);
                uint32_t bl0 = __float_as_uint(cvt_tf32(w0 - bh0f));
                uint32_t bl1 = __float_as_uint(cvt_tf32(w1 - bh1f));
                #pragma unroll
                for (int mi = 0; mi < 2; mi++) {
                    MMA_TF32(acc[mi][ni], ah[mi], bh0, bh1);
                    MMA_TF32(acc[mi][ni], ah[mi], bl0, bl1);
                }
            }
        }
        __syncthreads();
    }

    #pragma unroll
    for (int mi = 0; mi < 2; mi++) {
        int r0 = m0 + wm + mi * 16 + g;
        #pragma unroll
        for (int ni = 0; ni < 8; ni++) {
            int cc = n0 + wn + ni * 8 + ii * 2;
            float b0v = __ldg(&bias[cc]);
            float b1v = __ldg(&bias[cc + 1]);
            float2 o0 = make_float2(acc[mi][ni][0] + b0v, acc[mi][ni][1] + b1v);
            float2 o1 = make_float2(acc[mi][ni][2] + b0v, acc[mi][ni][3] + b1v);
            *(float2*)&C[(size_t)r0 * N + cc] = o0;
            *(float2*)&C[(size_t)(r0 + 8) * N + cc] = o1;
        }
    }
}

// ===========================================================================
// Two-level grid barrier: 8 group counters (16 blocks each) -> root -> epoch.
// Arrival serialization: 16-deep per group line (parallel across 8 lines)
// + 8-deep at root, vs 128-deep single-line before.
// ===========================================================================
__device__ __forceinline__ void grid_barrier_step(unsigned t1, int grp)
{
    __syncthreads();
    if (threadIdx.x == 0) {
        unsigned old;
        asm volatile("atom.release.gpu.global.add.u32 %0, [%1], %2;"
                     : "=r"(old) : "l"(&g_cnt[grp][0]), "r"(1u) : "memory");
        if (old + 1u == 16u * t1) {
            unsigned o2;
            asm volatile("atom.release.gpu.global.add.u32 %0, [%1], %2;"
                         : "=r"(o2) : "l"(&g_root[0]), "r"(1u) : "memory");
            if (o2 + 1u == 8u * t1) {
                asm volatile("st.release.gpu.global.u32 [%0], %1;"
                             :: "l"(&g_epoch[0]), "r"(t1) : "memory");
            } else {
                unsigned e;
                do {
                    __nanosleep(16);
                    asm volatile("ld.acquire.gpu.global.u32 %0, [%1];"
                                 : "=r"(e) : "l"(&g_epoch[0]) : "memory");
                } while (e < t1);
            }
        } else {
            unsigned e;
            do {
                __nanosleep(16);
                asm volatile("ld.acquire.gpu.global.u32 %0, [%1];"
                             : "=r"(e) : "l"(&g_epoch[0]) : "memory");
            } while (e < t1);
        }
    }
    __syncthreads();
}

// ===========================================================================
// Persistent LSTM layer — transposed recurrence z^T = R^T · h^T.
// 128 blocks x 512 threads (16 warps = 8 K-slices x 2 row-halves).
// zx prefetch for step t+1 issued BEFORE the barrier (hidden in the wait).
// ===========================================================================
#define ZS_LD 72
#define LSTM_SMEM_BYTES ((32768 + 8 * 32 * ZS_LD) * 4)   // 204800 B

__global__ __launch_bounds__(512, 1)
void lstm_mma_kernel(const float* __restrict__ zx,     // [B*TT][G4], row=b*TT+t
                     const float* __restrict__ Rp,     // packed A-frags
                     float* __restrict__ hpH0, float* __restrict__ hpH1,
                     float* __restrict__ hseq,         // [B][TT][UU] or null
                     float* __restrict__ hlast)        // [B][UU] or null
{
    extern __shared__ float dsm[];
    float* Rs   = dsm;                     // 32768 floats
    float* zsum = dsm + 32768;             // 8*32*ZS_LD floats

    const int tid  = threadIdx.x;
    const int b    = blockIdx.x;           // 0..127
    const int grp  = b >> 4;               // barrier group 0..7
    const int u0   = b * 8;
    const int lane = tid & 31, wid = tid >> 5;
    const int ks   = wid & 7;              // K-slice
    const int hf   = wid >> 3;             // row half
    const int g    = lane >> 2, ii = lane & 3;
    const int lane4 = lane * 4;
    const int ksl  = ks * 16;              // ktile base
    const int ntb  = hf * 4;               // nt base

    // load this block's packed R (A-frags) into smem, once
    {
        const float4* src = (const float4*)(Rp + (size_t)b * 32768);
        float4* dst = (float4*)Rs;
        #pragma unroll
        for (int q = 0; q < 16; q++)
            dst[q * 512 + tid] = __ldg(&src[q * 512 + tid]);
    }
    __syncthreads();

    // gating ownership: ONE item per thread: (row, u0+j0)
    const int row = tid >> 3, j0 = tid & 7;
    float c = 0.f;

    // h^T B-frag write index (kt == b for this block's units)
    const int pw = ((b * 8 + (row >> 3)) * 32 + (row & 7) * 4 + (j0 & 3)) * 2 + (j0 >> 2);
    const float* zrow = zx + (size_t)row * (TT * G4) + u0 + j0;

    // prefetch zx for step 0
    float zxv[4];
    #pragma unroll
    for (int q = 0; q < 4; q++) zxv[q] = __ldcs(zrow + q * UU);

    for (int t = 0; t < TT; t++) {
        const float* Ain  = (t & 1) ? hpH1 : hpH0;
        float*       Aout = (t & 1) ? hpH0 : hpH1;
        const float2* hp2 = (const float2*)Ain;

        float acc[2][4][4];
        #pragma unroll
        for (int mt = 0; mt < 2; mt++)
            #pragma unroll
            for (int nt = 0; nt < 4; nt++)
                #pragma unroll
                for (int q = 0; q < 4; q++) acc[mt][nt][q] = 0.f;

        // B-frag double buffer
        uint32_t bbuf[2][4][2];
        #pragma unroll
        for (int nt = 0; nt < 4; nt++) {
            float2 v = __ldcg(&hp2[(ksl * 8 + ntb + nt) * 32 + lane]);
            bbuf[0][nt][0] = __float_as_uint(v.x);
            bbuf[0][nt][1] = __float_as_uint(v.y);
        }

        #pragma unroll
        for (int kt = 0; kt < 16; kt++) {
            const int cur = kt & 1;
            if (kt < 15) {
                #pragma unroll
                for (int nt = 0; nt < 4; nt++) {
                    float2 v = __ldcg(&hp2[((ksl + kt + 1) * 8 + ntb + nt) * 32 + lane]);
                    bbuf[cur ^ 1][nt][0] = __float_as_uint(v.x);
                    bbuf[cur ^ 1][nt][1] = __float_as_uint(v.y);
                }
            }
            uint32_t a0[4], a1[4];
            *(float4*)a0 = *(const float4*)&Rs[((ksl + kt) * 2 + 0) * 128 + lane4];
            *(float4*)a1 = *(const float4*)&Rs[((ksl + kt) * 2 + 1) * 128 + lane4];
            #pragma unroll
            for (int nt = 0; nt < 4; nt++) {
                MMA_TF32(acc[0][nt], a0, bbuf[cur][nt][0], bbuf[cur][nt][1]);
                MMA_TF32(acc[1][nt], a1, bbuf[cur][nt][0], bbuf[cur][nt][1]);
            }
        }

        // store partial z^T: slot ks, rows m, cols ntb.. (disjoint between hf)
        #pragma unroll
        for (int mt = 0; mt < 2; mt++)
            #pragma unroll
            for (int nt = 0; nt < 4; nt++) {
                int off = (ks * 32 + mt * 16 + g) * ZS_LD + (ntb + nt) * 8 + ii * 2;
                *(float2*)&zsum[off] = make_float2(acc[mt][nt][0], acc[mt][nt][1]);
                *(float2*)&zsum[off + 8 * ZS_LD] = make_float2(acc[mt][nt][2], acc[mt][nt][3]);
            }
        __syncthreads();

        // reduce 8 K-slice partials for this thread's single gating item
        float z[4] = {0.f, 0.f, 0.f, 0.f};
        #pragma unroll
        for (int w = 0; w < 8; w++) {
            int base = w * 32 * ZS_LD + j0 * ZS_LD + row;
            #pragma unroll
            for (int gq = 0; gq < 4; gq++)
                z[gq] += zsum[base + gq * 8 * ZS_LD];
        }

        // gating (c in register); write h^T B-frag packed + exact hseq/hlast
        {
            int u = u0 + j0;
            float zi = z[0] + zxv[0];
            float zf = z[1] + zxv[1];
            float zg = z[2] + zxv[2];
            float zo = z[3] + zxv[3];
            float ig = 1.f / (1.f + __expf(-zi));
            float fg = 1.f / (1.f + __expf(-zf));
            float og = 1.f / (1.f + __expf(-zo));
            c = fmaf(fg, c, ig * zg);
            float hn = og * c;
            __stcg(&Aout[pw], cvt_tf32(hn));
            if (hseq) hseq[(size_t)row * (TT * UU) + (size_t)t * UU + u] = hn;
            if (hlast && t == TT - 1) hlast[row * UU + u] = hn;
        }

        if (t != TT - 1) {
            // prefetch NEXT step's zx before the barrier (independent of h)
            const float* zn = zrow + (size_t)(t + 1) * G4;
            #pragma unroll
            for (int q = 0; q < 4; q++) zxv[q] = __ldcs(zn + q * UU);
            grid_barrier_step((unsigned)(t + 1), grp);
        }
    }
}

// ===========================================================================
// LayerNorm + tanh
// ===========================================================================
__global__ __launch_bounds__(256, 4)
void ln_tanh_kernel(const float* __restrict__ in, float* __restrict__ out,
                    const float* __restrict__ gamma, const float* __restrict__ beta)
{
    const int row = blockIdx.x;
    const float* xr = in + (size_t)row * UU;
    float* yr = out + (size_t)row * UU;
    const int tid = threadIdx.x;

    float v[4];
    float s = 0.f, sq = 0.f;
    #pragma unroll
    for (int q = 0; q < 4; q++) {
        v[q] = xr[tid + q * 256];
        s += v[q];
        sq = fmaf(v[q], v[q], sq);
    }
    __shared__ float sm1[8], sm2[8];
    #pragma unroll
    for (int o = 16; o > 0; o >>= 1) {
        s  += __shfl_xor_sync(0xffffffffu, s, o);
        sq += __shfl_xor_sync(0xffffffffu, sq, o);
    }
    if ((tid & 31) == 0) { sm1[tid >> 5] = s; sm2[tid >> 5] = sq; }
    __syncthreads();
    __shared__ float s_mu, s_inv;
    if (tid == 0) {
        float ts = 0.f, tq = 0.f;
        #pragma unroll
        for (int w = 0; w < 8; w++) { ts += sm1[w]; tq += sm2[w]; }
        float mu = ts * (1.f / UU);
        float var = tq * (1.f / UU) - mu * mu;
        s_mu = mu;
        s_inv = rsqrtf(var + LN_EPS);
    }
    __syncthreads();
    float mu = s_mu, inv = s_inv;
    #pragma unroll
    for (int q = 0; q < 4; q++) {
        int idx = tid + q * 256;
        float y = (v[q] - mu) * inv * gamma[idx] + beta[idx];
        yr[idx] = tanhf(y);
    }
}

// ===========================================================================
// Per-layer init: zero packed h0 (ping), reset all barrier state
// ===========================================================================
__global__ void init_kernel(float* __restrict__ hH)
{
    int i = blockIdx.x * blockDim.x + threadIdx.x;
    if (i < 8) g_cnt[i][0] = 0u;
    if (i == 8) g_root[0] = 0u;
    if (i == 9) g_epoch[0] = 0u;
    if (i < 128 * 8 * 32 * 2) hH[i] = 0.f;
}

// ===========================================================================
// Launch: 10 graph nodes.  Order per layer: pack, init, gemm, lstm, ln
// ===========================================================================
extern "C" void kernel_launch(void* const* d_in, const int* in_sizes, int n_in,
                              void* d_out, int out_size)
{
    const float* x      = (const float*)d_in[0];
    const float* W1     = (const float*)d_in[1];
    const float* R1     = (const float*)d_in[2];
    const float* b1     = (const float*)d_in[3];
    const float* gamma1 = (const float*)d_in[4];
    const float* beta1  = (const float*)d_in[5];
    const float* W2     = (const float*)d_in[6];
    const float* R2     = (const float*)d_in[7];
    const float* b2     = (const float*)d_in[8];
    const float* gamma2 = (const float*)d_in[9];
    const float* beta2  = (const float*)d_in[10];
    float* out = (float*)d_out;

    float *zx, *hseq, *rp, *hpH0, *hpH1, *hlast;
    cudaGetSymbolAddress((void**)&zx,    g_zx);
    cudaGetSymbolAddress((void**)&hseq,  g_hseq);
    cudaGetSymbolAddress((void**)&rp,    g_rp2);
    cudaGetSymbolAddress((void**)&hlast, g_hlast);
    { void* p; cudaGetSymbolAddress(&p, g_hp_hi); hpH0 = (float*)p; hpH1 = hpH0 + 128 * 8 * 32 * 2; }

    cudaFuncSetAttribute(gemm_tf32_kernel,
                         cudaFuncAttributeMaxDynamicSharedMemorySize, GEMM_SMEM_BYTES);
    cudaFuncSetAttribute(lstm_mma_kernel,
                         cudaFuncAttributeMaxDynamicSharedMemorySize, LSTM_SMEM_BYTES);

    const int M = BB * TT;                       // 32768
    const dim3 ggrid(G4 / 128, M / 128);         // (32, 256)
    const int initg = (128 * 8 * 32 * 2 + 255) / 256;
    const int packg = (128 * 128 * 2 * 32) / 256;

    // ---- Layer 1 ----
    pack_r3_kernel<<<packg, 256>>>(R1, rp);
    init_kernel<<<initg, 256>>>(hpH0);
    gemm_tf32_kernel<<<ggrid, 256, GEMM_SMEM_BYTES>>>(x, W1, b1, zx, M, G4, DD);
    lstm_mma_kernel<<<128, 512, LSTM_SMEM_BYTES>>>(zx, rp, hpH0, hpH1, hseq, (float*)nullptr);
    ln_tanh_kernel<<<M, 256>>>(hseq, hseq, gamma1, beta1);

    // ---- Layer 2 ----
    pack_r3_kernel<<<packg, 256>>>(R2, rp);
    init_kernel<<<initg, 256>>>(hpH0);
    gemm_tf32_kernel<<<ggrid, 256, GEMM_SMEM_BYTES>>>(hseq, W2, b2, zx, M, G4, UU);
    lstm_mma_kernel<<<128, 512, LSTM_SMEM_BYTES>>>(zx, rp, hpH0, hpH1, (float*)nullptr, hlast);
    ln_tanh_kernel<<<BB, 256>>>(hlast, out, gamma2, beta2);
}

// round 15
// speedup vs baseline: 1.0567x; 1.0567x over previous
#include <cuda_runtime.h>
#include <math.h>
#include <stdint.h>

// Problem constants
#define BB 64
#define TT 512
#define DD 512
#define UU 1024
#define G4 4096          // 4*UU
#define LN_EPS 1e-3f

// ---------------------------------------------------------------------------
// Scratch (device globals — no allocation allowed)
// ---------------------------------------------------------------------------
__device__ float g_zx[(size_t)BB * TT * G4];     // 512 MiB, reused by both layers
__device__ float g_hseq[(size_t)BB * TT * UU];   // 128 MiB
// W pre-split tf32 hi/lo planes: [plane 2][K*N], reused by both layers
__device__ float g_wp[(size_t)2 * UU * G4];      // 32 MiB
// packed R^T as A-frags: [block 128][kt 128][mt 2][lane 32][4]  (tf32-hi)
__device__ float g_rp2[(size_t)128 * 128 * 2 * 32 * 4];   // 16 MiB
// packed h^T as B-frags: [kt 128][nt 8][lane 32][2 slots], ping/pong
__device__ float g_hp_hi[2][128 * 8 * 32 * 2];   // 256KB each
__device__ float g_hlast[BB * UU];
// single-level barrier (R13-validated): counter + epoch on separate lines
__device__ __align__(128) unsigned g_barcnt[32];
__device__ __align__(128) unsigned g_epoch[32];

// ---------------------------------------------------------------------------
// Helpers
// ---------------------------------------------------------------------------
__device__ __forceinline__ float cvt_tf32(float a) {
    float r;
    asm("cvt.rna.tf32.f32 %0, %1;" : "=f"(r) : "f"(a));
    return r;
}

__device__ __forceinline__ void cp16(void* s, const void* g) {
    uint32_t sa = (uint32_t)__cvta_generic_to_shared(s);
    asm volatile("cp.async.cg.shared.global [%0], [%1], 16;" :: "r"(sa), "l"(g));
}
#define CP_COMMIT()  asm volatile("cp.async.commit_group;" ::: "memory")
#define CP_WAIT(n)   asm volatile("cp.async.wait_group %0;" :: "n"(n) : "memory")

#define MMA_TF32(d, a, b0v, b1v) \
    asm volatile("mma.sync.aligned.m16n8k8.row.col.f32.tf32.tf32.f32 " \
        "{%0,%1,%2,%3}, {%4,%5,%6,%7}, {%8,%9}, {%0,%1,%2,%3};" \
        : "+f"((d)[0]), "+f"((d)[1]), "+f"((d)[2]), "+f"((d)[3]) \
        : "r"((a)[0]), "r"((a)[1]), "r"((a)[2]), "r"((a)[3]), \
          "r"(b0v), "r"(b1v))

// ===========================================================================
// Pack W into tf32 hi/lo planes (elementwise, float4 per thread).
// ===========================================================================
__global__ __launch_bounds__(256)
void pack_w_kernel(const float* __restrict__ W, float* __restrict__ Wh,
                   float* __restrict__ Wl, int n4)
{
    int i = blockIdx.x * blockDim.x + threadIdx.x;
    if (i >= n4) return;
    float4 v = __ldg((const float4*)W + i);
    float4 hi, lo;
    hi.x = cvt_tf32(v.x); lo.x = cvt_tf32(v.x - hi.x);
    hi.y = cvt_tf32(v.y); lo.y = cvt_tf32(v.y - hi.y);
    hi.z = cvt_tf32(v.z); lo.z = cvt_tf32(v.z - hi.z);
    hi.w = cvt_tf32(v.w); lo.w = cvt_tf32(v.w - hi.w);
    ((float4*)Wh)[i] = hi;
    ((float4*)Wl)[i] = lo;
}

// ===========================================================================
// Pack R^T (tf32-hi) into per-block A-frag layout (unchanged).
// ===========================================================================
__global__ __launch_bounds__(256)
void pack_r3_kernel(const float* __restrict__ R, float* __restrict__ Rp)
{
    int i = blockIdx.x * blockDim.x + threadIdx.x;   // float4 index (2^20 total)
    int lane = i & 31;
    int mt   = (i >> 5) & 1;
    int kt   = (i >> 6) & 127;
    int b    = i >> 13;
    int g  = lane >> 2, ii = lane & 3;
    int m0 = mt * 16 + g, m1 = m0 + 8;
    int col0 = (m0 >> 3) * UU + b * 8 + (m0 & 7);
    int col1 = (m1 >> 3) * UU + b * 8 + (m1 & 7);
    int r0 = kt * 8 + ii;
    float4 o;
    o.x = cvt_tf32(__ldg(&R[(size_t)r0 * G4 + col0]));
    o.y = cvt_tf32(__ldg(&R[(size_t)r0 * G4 + col1]));
    o.z = cvt_tf32(__ldg(&R[(size_t)(r0 + 4) * G4 + col0]));
    o.w = cvt_tf32(__ldg(&R[(size_t)(r0 + 4) * G4 + col1]));
    *(float4*)&Rp[(size_t)i * 4] = o;
}

// ===========================================================================
// 2xTF32 GEMM (Ah*Bh + Ah*Bl), cp.async double-buffered.
// B operand pre-split into hi/lo planes (no cvt in the B path).
// Block 128x128, BK=32, 256 threads (8 warps: 4m x 2n, warp tile 32x64).
// ===========================================================================
#define GBK   32
#define A_LD  36
#define B_LD  136
#define ASZ   (128 * A_LD)
#define BSZ   (GBK * B_LD)
#define GEMM_SMEM_BYTES ((2 * ASZ + 4 * BSZ) * 4)   // 106496 B

__global__ __launch_bounds__(256, 2)
void gemm_tf32_kernel(const float* __restrict__ A, const float* __restrict__ Wh,
                      const float* __restrict__ Wl,
                      const float* __restrict__ bias, float* __restrict__ C,
                      int M, int N, int K)
{
    extern __shared__ float sm[];
    float* Asm[2] = { sm, sm + ASZ };
    float* Bh[2]  = { sm + 2 * ASZ, sm + 2 * ASZ + BSZ };
    float* Bl[2]  = { sm + 2 * ASZ + 2 * BSZ, sm + 2 * ASZ + 3 * BSZ };

    const int tid  = threadIdx.x;
    const int m0   = blockIdx.y * 128;
    const int n0   = blockIdx.x * 128;
    const int lane = tid & 31, wid = tid >> 5;
    const int wm   = (wid & 3) * 32;
    const int wn   = (wid >> 2) * 64;
    const int g    = lane >> 2, ii = lane & 3;

    const int a_r = tid >> 3, a_c = (tid & 7) * 4;
    const int b_r = tid >> 5, b_c = (tid & 31) * 4;

    float acc[2][8][4];
    #pragma unroll
    for (int mi = 0; mi < 2; mi++)
        #pragma unroll
        for (int ni = 0; ni < 8; ni++)
            #pragma unroll
            for (int q = 0; q < 4; q++) acc[mi][ni][q] = 0.f;

    const int nk = K >> 5;

    {
        #pragma unroll
        for (int p = 0; p < 4; p++)
            cp16(&Asm[0][(a_r + p * 32) * A_LD + a_c],
                 &A[(size_t)(m0 + a_r + p * 32) * K + a_c]);
        #pragma unroll
        for (int p = 0; p < 4; p++) {
            size_t go = (size_t)(b_r + p * 8) * N + n0 + b_c;
            cp16(&Bh[0][(b_r + p * 8) * B_LD + b_c], &Wh[go]);
            cp16(&Bl[0][(b_r + p * 8) * B_LD + b_c], &Wl[go]);
        }
        CP_COMMIT();
    }

    for (int ch = 0; ch < nk; ch++) {
        const int buf = ch & 1;
        if (ch + 1 < nk) {
            const int k0 = (ch + 1) << 5;
            #pragma unroll
            for (int p = 0; p < 4; p++)
                cp16(&Asm[buf ^ 1][(a_r + p * 32) * A_LD + a_c],
                     &A[(size_t)(m0 + a_r + p * 32) * K + k0 + a_c]);
            #pragma unroll
            for (int p = 0; p < 4; p++) {
                size_t go = (size_t)(k0 + b_r + p * 8) * N + n0 + b_c;
                cp16(&Bh[buf ^ 1][(b_r + p * 8) * B_LD + b_c], &Wh[go]);
                cp16(&Bl[buf ^ 1][(b_r + p * 8) * B_LD + b_c], &Wl[go]);
            }
            CP_COMMIT();
            CP_WAIT(1);
        } else {
            CP_WAIT(0);
        }
        __syncthreads();

        const float* Ab  = Asm[buf];
        const float* Bbh = Bh[buf];
        const float* Bbl = Bl[buf];
        #pragma unroll
        for (int ks = 0; ks < 4; ks++) {
            const int kb = ks * 8;
            uint32_t ah[2][4];
            #pragma unroll
            for (int mi = 0; mi < 2; mi++) {
                int r0 = (wm + mi * 16 + g) * A_LD + kb + ii;
                int r8 = r0 + 8 * A_LD;
                ah[mi][0] = __float_as_uint(cvt_tf32(Ab[r0]));
                ah[mi][1] = __float_as_uint(cvt_tf32(Ab[r8]));
                ah[mi][2] = __float_as_uint(cvt_tf32(Ab[r0 + 4]));
                ah[mi][3] = __float_as_uint(cvt_tf32(Ab[r8 + 4]));
            }
            #pragma unroll
            for (int ni = 0; ni < 8; ni++) {
                int nb = wn + ni * 8 + g;
                uint32_t bh0 = __float_as_uint(Bbh[(kb + ii) * B_LD + nb]);
                uint32_t bh1 = __float_as_uint(Bbh[(kb + ii + 4) * B_LD + nb]);
                uint32_t bl0 = __float_as_uint(Bbl[(kb + ii) * B_LD + nb]);
                uint32_t bl1 = __float_as_uint(Bbl[(kb + ii + 4) * B_LD + nb]);
                #pragma unroll
                for (int mi = 0; mi < 2; mi++) {
                    MMA_TF32(acc[mi][ni], ah[mi], bh0, bh1);
                    MMA_TF32(acc[mi][ni], ah[mi], bl0, bl1);
                }
            }
        }
        __syncthreads();
    }

    #pragma unroll
    for (int mi = 0; mi < 2; mi++) {
        int r0 = m0 + wm + mi * 16 + g;
        #pragma unroll
        for (int ni = 0; ni < 8; ni++) {
            int cc = n0 + wn + ni * 8 + ii * 2;
            float b0v = __ldg(&bias[cc]);
            float b1v = __ldg(&bias[cc + 1]);
            float2 o0 = make_float2(acc[mi][ni][0] + b0v, acc[mi][ni][1] + b1v);
            float2 o1 = make_float2(acc[mi][ni][2] + b0v, acc[mi][ni][3] + b1v);
            *(float2*)&C[(size_t)r0 * N + cc] = o0;
            *(float2*)&C[(size_t)(r0 + 8) * N + cc] = o1;
        }
    }
}

// ===========================================================================
// Single-level grid barrier (R13-validated: fastest measured variant)
// ===========================================================================
__device__ __forceinline__ void grid_barrier_step(unsigned t1)
{
    __syncthreads();
    if (threadIdx.x == 0) {
        unsigned old;
        asm volatile("atom.release.gpu.global.add.u32 %0, [%1], %2;"
                     : "=r"(old) : "l"(&g_barcnt[0]), "r"(1u) : "memory");
        if (old + 1u == 128u * t1) {
            asm volatile("st.release.gpu.global.u32 [%0], %1;"
                         :: "l"(&g_epoch[0]), "r"(t1) : "memory");
        } else {
            unsigned e;
            do {
                __nanosleep(32);
                asm volatile("ld.acquire.gpu.global.u32 %0, [%1];"
                             : "=r"(e) : "l"(&g_epoch[0]) : "memory");
            } while (e < t1);
        }
    }
    __syncthreads();
}

// ===========================================================================
// Persistent LSTM layer — transposed recurrence z^T = R^T · h^T.
// 128 blocks x 512 threads (16 warps = 8 K-slices x 2 row-halves).
// zx prefetch for step t+1 issued BEFORE the barrier (hidden in the wait).
// ===========================================================================
#define ZS_LD 72
#define LSTM_SMEM_BYTES ((32768 + 8 * 32 * ZS_LD) * 4)   // 204800 B

__global__ __launch_bounds__(512, 1)
void lstm_mma_kernel(const float* __restrict__ zx,     // [B*TT][G4], row=b*TT+t
                     const float* __restrict__ Rp,     // packed A-frags
                     float* __restrict__ hpH0, float* __restrict__ hpH1,
                     float* __restrict__ hseq,         // [B][TT][UU] or null
                     float* __restrict__ hlast)        // [B][UU] or null
{
    extern __shared__ float dsm[];
    float* Rs   = dsm;                     // 32768 floats
    float* zsum = dsm + 32768;             // 8*32*ZS_LD floats

    const int tid  = threadIdx.x;
    const int b    = blockIdx.x;           // 0..127
    const int u0   = b * 8;
    const int lane = tid & 31, wid = tid >> 5;
    const int ks   = wid & 7;              // K-slice
    const int hf   = wid >> 3;             // row half
    const int g    = lane >> 2, ii = lane & 3;
    const int lane4 = lane * 4;
    const int ksl  = ks * 16;              // ktile base
    const int ntb  = hf * 4;               // nt base

    // load this block's packed R (A-frags) into smem, once
    {
        const float4* src = (const float4*)(Rp + (size_t)b * 32768);
        float4* dst = (float4*)Rs;
        #pragma unroll
        for (int q = 0; q < 16; q++)
            dst[q * 512 + tid] = __ldg(&src[q * 512 + tid]);
    }
    __syncthreads();

    // gating ownership: ONE item per thread: (row, u0+j0)
    const int row = tid >> 3, j0 = tid & 7;
    float c = 0.f;

    // h^T B-frag write index (kt == b for this block's units)
    const int pw = ((b * 8 + (row >> 3)) * 32 + (row & 7) * 4 + (j0 & 3)) * 2 + (j0 >> 2);
    const float* zrow = zx + (size_t)row * (TT * G4) + u0 + j0;

    // prefetch zx for step 0
    float zxv[4];
    #pragma unroll
    for (int q = 0; q < 4; q++) zxv[q] = __ldcs(zrow + q * UU);

    for (int t = 0; t < TT; t++) {
        const float* Ain  = (t & 1) ? hpH1 : hpH0;
        float*       Aout = (t & 1) ? hpH0 : hpH1;
        const float2* hp2 = (const float2*)Ain;

        float acc[2][4][4];
        #pragma unroll
        for (int mt = 0; mt < 2; mt++)
            #pragma unroll
            for (int nt = 0; nt < 4; nt++)
                #pragma unroll
                for (int q = 0; q < 4; q++) acc[mt][nt][q] = 0.f;

        // B-frag double buffer
        uint32_t bbuf[2][4][2];
        #pragma unroll
        for (int nt = 0; nt < 4; nt++) {
            float2 v = __ldcg(&hp2[(ksl * 8 + ntb + nt) * 32 + lane]);
            bbuf[0][nt][0] = __float_as_uint(v.x);
            bbuf[0][nt][1] = __float_as_uint(v.y);
        }

        #pragma unroll
        for (int kt = 0; kt < 16; kt++) {
            const int cur = kt & 1;
            if (kt < 15) {
                #pragma unroll
                for (int nt = 0; nt < 4; nt++) {
                    float2 v = __ldcg(&hp2[((ksl + kt + 1) * 8 + ntb + nt) * 32 + lane]);
                    bbuf[cur ^ 1][nt][0] = __float_as_uint(v.x);
                    bbuf[cur ^ 1][nt][1] = __float_as_uint(v.y);
                }
            }
            uint32_t a0[4], a1[4];
            *(float4*)a0 = *(const float4*)&Rs[((ksl + kt) * 2 + 0) * 128 + lane4];
            *(float4*)a1 = *(const float4*)&Rs[((ksl + kt) * 2 + 1) * 128 + lane4];
            #pragma unroll
            for (int nt = 0; nt < 4; nt++) {
                MMA_TF32(acc[0][nt], a0, bbuf[cur][nt][0], bbuf[cur][nt][1]);
                MMA_TF32(acc[1][nt], a1, bbuf[cur][nt][0], bbuf[cur][nt][1]);
            }
        }

        // store partial z^T: slot ks, rows m, cols ntb.. (disjoint between hf)
        #pragma unroll
        for (int mt = 0; mt < 2; mt++)
            #pragma unroll
            for (int nt = 0; nt < 4; nt++) {
                int off = (ks * 32 + mt * 16 + g) * ZS_LD + (ntb + nt) * 8 + ii * 2;
                *(float2*)&zsum[off] = make_float2(acc[mt][nt][0], acc[mt][nt][1]);
                *(float2*)&zsum[off + 8 * ZS_LD] = make_float2(acc[mt][nt][2], acc[mt][nt][3]);
            }
        __syncthreads();

        // reduce 8 K-slice partials for this thread's single gating item
        float z[4] = {0.f, 0.f, 0.f, 0.f};
        #pragma unroll
        for (int w = 0; w < 8; w++) {
            int base = w * 32 * ZS_LD + j0 * ZS_LD + row;
            #pragma unroll
            for (int gq = 0; gq < 4; gq++)
                z[gq] += zsum[base + gq * 8 * ZS_LD];
        }

        // gating (c in register); write h^T B-frag packed + exact hseq/hlast
        {
            int u = u0 + j0;
            float zi = z[0] + zxv[0];
            float zf = z[1] + zxv[1];
            float zg = z[2] + zxv[2];
            float zo = z[3] + zxv[3];
            float ig = 1.f / (1.f + __expf(-zi));
            float fg = 1.f / (1.f + __expf(-zf));
            float og = 1.f / (1.f + __expf(-zo));
            c = fmaf(fg, c, ig * zg);
            float hn = og * c;
            __stcg(&Aout[pw], cvt_tf32(hn));
            if (hseq) hseq[(size_t)row * (TT * UU) + (size_t)t * UU + u] = hn;
            if (hlast && t == TT - 1) hlast[row * UU + u] = hn;
        }

        if (t != TT - 1) {
            // prefetch NEXT step's zx before the barrier (independent of h)
            const float* zn = zrow + (size_t)(t + 1) * G4;
            #pragma unroll
            for (int q = 0; q < 4; q++) zxv[q] = __ldcs(zn + q * UU);
            grid_barrier_step((unsigned)(t + 1));
        }
    }
}

// ===========================================================================
// LayerNorm + tanh
// ===========================================================================
__global__ __launch_bounds__(256, 4)
void ln_tanh_kernel(const float* __restrict__ in, float* __restrict__ out,
                    const float* __restrict__ gamma, const float* __restrict__ beta)
{
    const int row = blockIdx.x;
    const float* xr = in + (size_t)row * UU;
    float* yr = out + (size_t)row * UU;
    const int tid = threadIdx.x;

    float v[4];
    float s = 0.f, sq = 0.f;
    #pragma unroll
    for (int q = 0; q < 4; q++) {
        v[q] = xr[tid + q * 256];
        s += v[q];
        sq = fmaf(v[q], v[q], sq);
    }
    __shared__ float sm1[8], sm2[8];
    #pragma unroll
    for (int o = 16; o > 0; o >>= 1) {
        s  += __shfl_xor_sync(0xffffffffu, s, o);
        sq += __shfl_xor_sync(0xffffffffu, sq, o);
    }
    if ((tid & 31) == 0) { sm1[tid >> 5] = s; sm2[tid >> 5] = sq; }
    __syncthreads();
    __shared__ float s_mu, s_inv;
    if (tid == 0) {
        float ts = 0.f, tq = 0.f;
        #pragma unroll
        for (int w = 0; w < 8; w++) { ts += sm1[w]; tq += sm2[w]; }
        float mu = ts * (1.f / UU);
        float var = tq * (1.f / UU) - mu * mu;
        s_mu = mu;
        s_inv = rsqrtf(var + LN_EPS);
    }
    __syncthreads();
    float mu = s_mu, inv = s_inv;
    #pragma unroll
    for (int q = 0; q < 4; q++) {
        int idx = tid + q * 256;
        float y = (v[q] - mu) * inv * gamma[idx] + beta[idx];
        yr[idx] = tanhf(y);
    }
}

// ===========================================================================
// Per-layer init: zero packed h0 (ping), reset barrier counter + epoch
// ===========================================================================
__global__ void init_kernel(float* __restrict__ hH)
{
    int i = blockIdx.x * blockDim.x + threadIdx.x;
    if (i == 0) { g_barcnt[0] = 0u; g_epoch[0] = 0u; }
    if (i < 128 * 8 * 32 * 2) hH[i] = 0.f;
}

// ===========================================================================
// Launch: 12 graph nodes.  Order per layer: pack_w, pack_r, init, gemm, lstm, ln
// ===========================================================================
extern "C" void kernel_launch(void* const* d_in, const int* in_sizes, int n_in,
                              void* d_out, int out_size)
{
    const float* x      = (const float*)d_in[0];
    const float* W1     = (const float*)d_in[1];
    const float* R1     = (const float*)d_in[2];
    const float* b1     = (const float*)d_in[3];
    const float* gamma1 = (const float*)d_in[4];
    const float* beta1  = (const float*)d_in[5];
    const float* W2     = (const float*)d_in[6];
    const float* R2     = (const float*)d_in[7];
    const float* b2     = (const float*)d_in[8];
    const float* gamma2 = (const float*)d_in[9];
    const float* beta2  = (const float*)d_in[10];
    float* out = (float*)d_out;

    float *zx, *hseq, *wp, *rp, *hpH0, *hpH1, *hlast;
    cudaGetSymbolAddress((void**)&zx,    g_zx);
    cudaGetSymbolAddress((void**)&hseq,  g_hseq);
    cudaGetSymbolAddress((void**)&wp,    g_wp);
    cudaGetSymbolAddress((void**)&rp,    g_rp2);
    cudaGetSymbolAddress((void**)&hlast, g_hlast);
    { void* p; cudaGetSymbolAddress(&p, g_hp_hi); hpH0 = (float*)p; hpH1 = hpH0 + 128 * 8 * 32 * 2; }

    cudaFuncSetAttribute(gemm_tf32_kernel,
                         cudaFuncAttributeMaxDynamicSharedMemorySize, GEMM_SMEM_BYTES);
    cudaFuncSetAttribute(lstm_mma_kernel,
                         cudaFuncAttributeMaxDynamicSharedMemorySize, LSTM_SMEM_BYTES);

    const int M = BB * TT;                       // 32768
    const dim3 ggrid(G4 / 128, M / 128);         // (32, 256)
    const int initg = (128 * 8 * 32 * 2 + 255) / 256;
    const int packg = (128 * 128 * 2 * 32) / 256;
    const int w1n4 = DD * G4 / 4, w2n4 = UU * G4 / 4;
    float* wlo1 = wp + (size_t)DD * G4;
    float* wlo2 = wp + (size_t)UU * G4;

    // ---- Layer 1 ----
    pack_w_kernel<<<(w1n4 + 255) / 256, 256>>>(W1, wp, wlo1, w1n4);
    pack_r3_kernel<<<packg, 256>>>(R1, rp);
    init_kernel<<<initg, 256>>>(hpH0);
    gemm_tf32_kernel<<<ggrid, 256, GEMM_SMEM_BYTES>>>(x, wp, wlo1, b1, zx, M, G4, DD);
    lstm_mma_kernel<<<128, 512, LSTM_SMEM_BYTES>>>(zx, rp, hpH0, hpH1, hseq, (float*)nullptr);
    ln_tanh_kernel<<<M, 256>>>(hseq, hseq, gamma1, beta1);

    // ---- Layer 2 ----
    pack_w_kernel<<<(w2n4 + 255) / 256, 256>>>(W2, wp, wlo2, w2n4);
    pack_r3_kernel<<<packg, 256>>>(R2, rp);
    init_kernel<<<initg, 256>>>(hpH0);
    gemm_tf32_kernel<<<ggrid, 256, GEMM_SMEM_BYTES>>>(hseq, wp, wlo2, b2, zx, M, G4, UU);
    lstm_mma_kernel<<<128, 512, LSTM_SMEM_BYTES>>>(zx, rp, hpH0, hpH1, (float*)nullptr, hlast);
    ln_tanh_kernel<<<BB, 256>>>(hlast, out, gamma2, beta2);
}